// round 1
// baseline (speedup 1.0000x reference)
#include <cuda_runtime.h>
#include <cstdint>

#define MAT 4096
#define SQ  1024
#define HD  128
#define NEG_BIG (-1e30f)

// Scratch (allocation-free rule: device globals)
__device__ float g_q[(size_t)MAT * MAT];
__device__ float g_k[(size_t)MAT * MAT];
__device__ float g_v[(size_t)MAT * MAT];
__device__ float g_att[(size_t)MAT * MAT];

__device__ __forceinline__ float tf32r(float x) {
    uint32_t u;
    asm("cvt.rna.tf32.f32 %0, %1;" : "=r"(u) : "f"(x));
    return __uint_as_float(u);
}

__device__ __forceinline__ void mma8(float c[4], const uint32_t a[4], const uint32_t b[2]) {
    asm volatile(
        "mma.sync.aligned.m16n8k8.row.col.f32.tf32.tf32.f32 "
        "{%0,%1,%2,%3},{%4,%5,%6,%7},{%8,%9},{%0,%1,%2,%3};\n"
        : "+f"(c[0]), "+f"(c[1]), "+f"(c[2]), "+f"(c[3])
        : "r"(a[0]), "r"(a[1]), "r"(a[2]), "r"(a[3]), "r"(b[0]), "r"(b[1]));
}

// ---------------------------------------------------------------------------
// GEMM: C[m][n] = sum_k A[m][k] * W[n][k]   (4096x4096x4096)
// BM=BN=128, BK=32, 256 threads (8 warps, 4x2), warp tile 32x64.
// doRope: fused RoPE epilogue (adjacent column pairs live in one thread).
// ---------------------------------------------------------------------------
#define GSTR 36
#define GBUF (128 * GSTR)

__global__ __launch_bounds__(256, 1) void gemm128(
    const float* __restrict__ A, const float* __restrict__ W, float* __restrict__ C,
    const float* __restrict__ cosT, const float* __restrict__ sinT, int doRope)
{
    extern __shared__ float sm[];
    float* As = sm;             // 2 buffers of [128][36]
    float* Bs = sm + 2 * GBUF;

    const int tid = threadIdx.x;
    const int bm = blockIdx.y, bn = blockIdx.x;
    const int lr  = tid >> 3;         // 0..31
    const int lc4 = (tid & 7) << 2;   // 0,4,..,28
    const float* Ap = A + (size_t)(bm * 128 + lr) * MAT + lc4;
    const float* Wp = W + (size_t)(bn * 128 + lr) * MAT + lc4;

    float4 ra[4], rb[4];
#pragma unroll
    for (int p = 0; p < 4; p++) {
        ra[p] = *reinterpret_cast<const float4*>(Ap + (size_t)(p * 32) * MAT);
        rb[p] = *reinterpret_cast<const float4*>(Wp + (size_t)(p * 32) * MAT);
    }
#pragma unroll
    for (int p = 0; p < 4; p++) {
        int row = p * 32 + lr;
        float4 va = ra[p];
        va.x = tf32r(va.x); va.y = tf32r(va.y); va.z = tf32r(va.z); va.w = tf32r(va.w);
        *reinterpret_cast<float4*>(As + row * GSTR + lc4) = va;
        float4 vb = rb[p];
        vb.x = tf32r(vb.x); vb.y = tf32r(vb.y); vb.z = tf32r(vb.z); vb.w = tf32r(vb.w);
        *reinterpret_cast<float4*>(Bs + row * GSTR + lc4) = vb;
    }
    __syncthreads();

    const int lane = tid & 31, wrp = tid >> 5;
    const int g = lane >> 2, t = lane & 3;
    const int m0 = (wrp & 3) * 32, n0 = (wrp >> 2) * 64;

    float acc[2][8][4];
#pragma unroll
    for (int i = 0; i < 2; i++)
#pragma unroll
        for (int j = 0; j < 8; j++)
#pragma unroll
            for (int q = 0; q < 4; q++) acc[i][j][q] = 0.f;

    const int nK = MAT / 32;
    for (int kt = 0; kt < nK; kt++) {
        const int cur = kt & 1;
        if (kt + 1 < nK) {
            size_t off = (size_t)(kt + 1) * 32;
#pragma unroll
            for (int p = 0; p < 4; p++) {
                ra[p] = *reinterpret_cast<const float4*>(Ap + (size_t)(p * 32) * MAT + off);
                rb[p] = *reinterpret_cast<const float4*>(Wp + (size_t)(p * 32) * MAT + off);
            }
        }
        const uint32_t* au = reinterpret_cast<const uint32_t*>(As + cur * GBUF);
        const uint32_t* bu = reinterpret_cast<const uint32_t*>(Bs + cur * GBUF);
#pragma unroll
        for (int ks = 0; ks < 4; ks++) {
            const int k0 = ks * 8;
            uint32_t af[2][4];
#pragma unroll
            for (int mt = 0; mt < 2; mt++) {
                const int r = m0 + mt * 16 + g;
                af[mt][0] = au[r * GSTR + k0 + t];
                af[mt][1] = au[(r + 8) * GSTR + k0 + t];
                af[mt][2] = au[r * GSTR + k0 + t + 4];
                af[mt][3] = au[(r + 8) * GSTR + k0 + t + 4];
            }
#pragma unroll
            for (int nt = 0; nt < 8; nt++) {
                const int n = n0 + nt * 8 + g;
                uint32_t bf[2] = { bu[n * GSTR + k0 + t], bu[n * GSTR + k0 + t + 4] };
                mma8(acc[0][nt], af[0], bf);
                mma8(acc[1][nt], af[1], bf);
            }
        }
        if (kt + 1 < nK) {
            float* ad = As + (cur ^ 1) * GBUF;
            float* bd = Bs + (cur ^ 1) * GBUF;
#pragma unroll
            for (int p = 0; p < 4; p++) {
                int row = p * 32 + lr;
                float4 va = ra[p];
                va.x = tf32r(va.x); va.y = tf32r(va.y); va.z = tf32r(va.z); va.w = tf32r(va.w);
                *reinterpret_cast<float4*>(ad + row * GSTR + lc4) = va;
                float4 vb = rb[p];
                vb.x = tf32r(vb.x); vb.y = tf32r(vb.y); vb.z = tf32r(vb.z); vb.w = tf32r(vb.w);
                *reinterpret_cast<float4*>(bd + row * GSTR + lc4) = vb;
            }
            __syncthreads();
        }
    }

#pragma unroll
    for (int mt = 0; mt < 2; mt++) {
        const int gm = bm * 128 + m0 + mt * 16 + g;
#pragma unroll
        for (int nt = 0; nt < 8; nt++) {
            const int cloc = n0 + nt * 8 + 2 * t;   // < 128
            const int gn = bn * 128 + cloc;
            float v0 = acc[mt][nt][0], v1 = acc[mt][nt][1];
            float v2 = acc[mt][nt][2], v3 = acc[mt][nt][3];
            if (doRope) {
                const int p  = cloc >> 1;           // pair index within head (BN==HD aligned)
                const int s0 = gm & (SQ - 1);       // sequence position (no 1024-crossing in tile)
                float cc0 = cosT[s0 * 64 + p],       ss0 = sinT[s0 * 64 + p];
                float cc1 = cosT[(s0 + 8) * 64 + p], ss1 = sinT[(s0 + 8) * 64 + p];
                float w0 = v0 * cc0 - v1 * ss0;
                float w1 = v0 * ss0 + v1 * cc0;
                float w2 = v2 * cc1 - v3 * ss1;
                float w3 = v2 * ss1 + v3 * cc1;
                v0 = w0; v1 = w1; v2 = w2; v3 = w3;
            }
            *reinterpret_cast<float2*>(C + (size_t)gm * MAT + gn)       = make_float2(v0, v1);
            *reinterpret_cast<float2*>(C + (size_t)(gm + 8) * MAT + gn) = make_float2(v2, v3);
        }
    }
}

// ---------------------------------------------------------------------------
// Flash attention: grid (S/128, H, B), 256 threads (8 warps x 16 query rows).
// K-tiles of 64; causal: kt in [0, 2*qt+1], mask only kt >= 2*qt.
// QK^T and P*V via tf32 mma; P staged through warp-private smem.
// ---------------------------------------------------------------------------
#define QSTR 132
#define KSTR 132
#define VSTR 136
#define PSTR 68

__global__ __launch_bounds__(256, 1) void attn128(
    const float* __restrict__ Q, const float* __restrict__ K,
    const float* __restrict__ V, float* __restrict__ O)
{
    extern __shared__ float sm[];
    float* Qs = sm;                       // [128][132]
    float* Ks = Qs + 128 * QSTR;          // [64][132]
    float* Vs = Ks + 64 * KSTR;           // [64][136]
    float* Ps = Vs + 64 * VSTR;           // 8 warps x [16][68]

    const int tid = threadIdx.x;
    const int qt = blockIdx.x, h = blockIdx.y, b = blockIdx.z;
    const int qbase = qt * 128;
    const size_t rowbase = (size_t)b * SQ;
    const float scale = 0.08838834764831845f;   // 1/sqrt(128)

    {   // load + scale + tf32-round Q tile
        const float* qp = Q + (rowbase + qbase) * MAT + h * HD;
#pragma unroll
        for (int i = 0; i < 16; i++) {
            int idx = tid + i * 256;          // 0..4095
            int row = idx >> 5;
            int c4  = (idx & 31) << 2;
            float4 v = *reinterpret_cast<const float4*>(qp + (size_t)row * MAT + c4);
            v.x = tf32r(v.x * scale); v.y = tf32r(v.y * scale);
            v.z = tf32r(v.z * scale); v.w = tf32r(v.w * scale);
            *reinterpret_cast<float4*>(Qs + row * QSTR + c4) = v;
        }
    }

    const int lane = tid & 31, wrp = tid >> 5;
    const int g = lane >> 2, t = lane & 3;
    const int r0 = wrp * 16;

    float o[16][4];
#pragma unroll
    for (int i = 0; i < 16; i++)
#pragma unroll
        for (int j = 0; j < 4; j++) o[i][j] = 0.f;
    float m0 = NEG_BIG, m1 = NEG_BIG, l0 = 0.f, l1 = 0.f;

    const int nkt = 2 * qt + 2;
    for (int kt = 0; kt < nkt; kt++) {
        __syncthreads();   // K/V/P reuse barrier (also orders Q store on kt==0)
        {
            const float* kp = K + (rowbase + kt * 64) * MAT + h * HD;
            const float* vp = V + (rowbase + kt * 64) * MAT + h * HD;
#pragma unroll
            for (int i = 0; i < 8; i++) {
                int idx = tid + i * 256;      // 0..2047
                int row = idx >> 5;
                int c4  = (idx & 31) << 2;
                float4 kv = *reinterpret_cast<const float4*>(kp + (size_t)row * MAT + c4);
                kv.x = tf32r(kv.x); kv.y = tf32r(kv.y); kv.z = tf32r(kv.z); kv.w = tf32r(kv.w);
                *reinterpret_cast<float4*>(Ks + row * KSTR + c4) = kv;
                float4 vv = *reinterpret_cast<const float4*>(vp + (size_t)row * MAT + c4);
                vv.x = tf32r(vv.x); vv.y = tf32r(vv.y); vv.z = tf32r(vv.z); vv.w = tf32r(vv.w);
                *reinterpret_cast<float4*>(Vs + row * VSTR + c4) = vv;
            }
        }
        __syncthreads();

        // S = Q * K^T (per warp: 16 rows x 64 keys, k=128)
        float sfr[8][4];
#pragma unroll
        for (int i = 0; i < 8; i++)
#pragma unroll
            for (int j = 0; j < 4; j++) sfr[i][j] = 0.f;

        const uint32_t* qsu = reinterpret_cast<const uint32_t*>(Qs);
        const uint32_t* ksu = reinterpret_cast<const uint32_t*>(Ks);
#pragma unroll
        for (int ks = 0; ks < 16; ks++) {
            const int k0 = ks * 8;
            uint32_t af[4] = {
                qsu[(r0 + g) * QSTR + k0 + t],
                qsu[(r0 + g + 8) * QSTR + k0 + t],
                qsu[(r0 + g) * QSTR + k0 + t + 4],
                qsu[(r0 + g + 8) * QSTR + k0 + t + 4] };
#pragma unroll
            for (int nt = 0; nt < 8; nt++) {
                uint32_t bf[2] = { ksu[(nt * 8 + g) * KSTR + k0 + t],
                                   ksu[(nt * 8 + g) * KSTR + k0 + t + 4] };
                mma8(sfr[nt], af, bf);
            }
        }

        if (kt >= 2 * qt) {   // diagonal tiles: causal mask
            const int qg0 = qbase + r0 + g;
            const int qg1 = qg0 + 8;
#pragma unroll
            for (int nt = 0; nt < 8; nt++) {
                const int kg = kt * 64 + nt * 8 + 2 * t;
                if (kg     > qg0) sfr[nt][0] = NEG_BIG;
                if (kg + 1 > qg0) sfr[nt][1] = NEG_BIG;
                if (kg     > qg1) sfr[nt][2] = NEG_BIG;
                if (kg + 1 > qg1) sfr[nt][3] = NEG_BIG;
            }
        }

        // online softmax
        float tm0 = NEG_BIG, tm1 = NEG_BIG;
#pragma unroll
        for (int nt = 0; nt < 8; nt++) {
            tm0 = fmaxf(tm0, fmaxf(sfr[nt][0], sfr[nt][1]));
            tm1 = fmaxf(tm1, fmaxf(sfr[nt][2], sfr[nt][3]));
        }
        tm0 = fmaxf(tm0, __shfl_xor_sync(0xffffffffu, tm0, 1));
        tm0 = fmaxf(tm0, __shfl_xor_sync(0xffffffffu, tm0, 2));
        tm1 = fmaxf(tm1, __shfl_xor_sync(0xffffffffu, tm1, 1));
        tm1 = fmaxf(tm1, __shfl_xor_sync(0xffffffffu, tm1, 2));

        const float mn0 = fmaxf(m0, tm0), mn1 = fmaxf(m1, tm1);
        const float a0 = __expf(m0 - mn0), a1 = __expf(m1 - mn1);
        float ls0 = 0.f, ls1 = 0.f;
        float* Pw = Ps + wrp * 16 * PSTR;
#pragma unroll
        for (int nt = 0; nt < 8; nt++) {
            const int col = nt * 8 + 2 * t;
            float p0 = __expf(sfr[nt][0] - mn0);
            float p1 = __expf(sfr[nt][1] - mn0);
            float p2 = __expf(sfr[nt][2] - mn1);
            float p3 = __expf(sfr[nt][3] - mn1);
            ls0 += p0 + p1; ls1 += p2 + p3;
            Pw[g * PSTR + col]           = tf32r(p0);
            Pw[g * PSTR + col + 1]       = tf32r(p1);
            Pw[(g + 8) * PSTR + col]     = tf32r(p2);
            Pw[(g + 8) * PSTR + col + 1] = tf32r(p3);
        }
        ls0 += __shfl_xor_sync(0xffffffffu, ls0, 1);
        ls0 += __shfl_xor_sync(0xffffffffu, ls0, 2);
        ls1 += __shfl_xor_sync(0xffffffffu, ls1, 1);
        ls1 += __shfl_xor_sync(0xffffffffu, ls1, 2);
        l0 = l0 * a0 + ls0;
        l1 = l1 * a1 + ls1;
        m0 = mn0; m1 = mn1;
#pragma unroll
        for (int nt = 0; nt < 16; nt++) {
            o[nt][0] *= a0; o[nt][1] *= a0; o[nt][2] *= a1; o[nt][3] *= a1;
        }
        __syncwarp();

        // O += P * V  (per warp: 16 rows x 128 d, k=64)
        const uint32_t* pu = reinterpret_cast<const uint32_t*>(Pw);
        const uint32_t* vu = reinterpret_cast<const uint32_t*>(Vs);
#pragma unroll
        for (int ks = 0; ks < 8; ks++) {
            const int k0 = ks * 8;
            uint32_t af[4] = {
                pu[g * PSTR + k0 + t],
                pu[(g + 8) * PSTR + k0 + t],
                pu[g * PSTR + k0 + t + 4],
                pu[(g + 8) * PSTR + k0 + t + 4] };
#pragma unroll
            for (int nt = 0; nt < 16; nt++) {
                uint32_t bf[2] = { vu[(k0 + t) * VSTR + nt * 8 + g],
                                   vu[(k0 + t + 4) * VSTR + nt * 8 + g] };
                mma8(o[nt], af, bf);
            }
        }
    }

    const float inv0 = 1.f / l0, inv1 = 1.f / l1;
    float* op  = O + (rowbase + qbase + r0 + g) * MAT + h * HD;
    float* op2 = op + (size_t)8 * MAT;
#pragma unroll
    for (int nt = 0; nt < 16; nt++) {
        const int col = nt * 8 + 2 * t;
        *reinterpret_cast<float2*>(op + col)  = make_float2(o[nt][0] * inv0, o[nt][1] * inv0);
        *reinterpret_cast<float2*>(op2 + col) = make_float2(o[nt][2] * inv1, o[nt][3] * inv1);
    }
}

// ---------------------------------------------------------------------------

#define GEMM_SMEM (4 * 128 * 36 * 4)                                    // 73728 B
#define ATTN_SMEM ((128 * QSTR + 64 * KSTR + 64 * VSTR + 8 * 16 * PSTR) * 4)  // 171008 B

extern "C" void kernel_launch(void* const* d_in, const int* in_sizes, int n_in,
                              void* d_out, int out_size)
{
    const float* x    = (const float*)d_in[0];
    const float* wq   = (const float*)d_in[1];
    const float* wk   = (const float*)d_in[2];
    const float* wv   = (const float*)d_in[3];
    const float* wo   = (const float*)d_in[4];
    const float* cosT = (const float*)d_in[5];
    const float* sinT = (const float*)d_in[6];
    float* out = (float*)d_out;

    cudaFuncSetAttribute(gemm128, cudaFuncAttributeMaxDynamicSharedMemorySize, GEMM_SMEM);
    cudaFuncSetAttribute(attn128, cudaFuncAttributeMaxDynamicSharedMemorySize, ATTN_SMEM);

    float *pq, *pk, *pv, *pa;
    cudaGetSymbolAddress((void**)&pq, g_q);
    cudaGetSymbolAddress((void**)&pk, g_k);
    cudaGetSymbolAddress((void**)&pv, g_v);
    cudaGetSymbolAddress((void**)&pa, g_att);

    dim3 gb(32, 32);
    gemm128<<<gb, 256, GEMM_SMEM>>>(x, wq, pq, cosT, sinT, 1);
    gemm128<<<gb, 256, GEMM_SMEM>>>(x, wk, pk, cosT, sinT, 1);
    gemm128<<<gb, 256, GEMM_SMEM>>>(x, wv, pv, cosT, sinT, 0);
    attn128<<<dim3(8, 32, 4), 256, ATTN_SMEM>>>(pq, pk, pv, pa);
    gemm128<<<gb, 256, GEMM_SMEM>>>(pa, wo, out, cosT, sinT, 0);
}

// round 4
// speedup vs baseline: 1.0567x; 1.0567x over previous
#include <cuda_runtime.h>
#include <cstdint>

#define MAT 4096
#define SQ  1024
#define HD  128
#define NEG_BIG (-1e30f)

// Scratch (allocation-free rule: device globals)
__device__ float g_q  [(size_t)MAT * MAT];
__device__ float g_k  [(size_t)MAT * MAT];
__device__ float g_v  [(size_t)MAT * MAT];
__device__ float g_att[(size_t)MAT * MAT];
__device__ float g_xr [(size_t)MAT * MAT];
__device__ float g_wqr[(size_t)MAT * MAT];
__device__ float g_wkr[(size_t)MAT * MAT];
__device__ float g_wvr[(size_t)MAT * MAT];
__device__ float g_wor[(size_t)MAT * MAT];

// ---------------------------------------------------------------------------
__device__ __forceinline__ float tf32r(float x) {
    uint32_t u;
    asm("cvt.rna.tf32.f32 %0, %1;" : "=r"(u) : "f"(x));
    return __uint_as_float(u);
}

__device__ __forceinline__ uint32_t smem_u32(const void* p) {
    uint32_t a;
    asm("{ .reg .u64 t; cvta.to.shared.u64 t, %1; cvt.u32.u64 %0, t; }" : "=r"(a) : "l"(p));
    return a;
}

__device__ __forceinline__ void mma8(float c[4], const uint32_t a[4], const uint32_t b[2]) {
    asm volatile(
        "mma.sync.aligned.m16n8k8.row.col.f32.tf32.tf32.f32 "
        "{%0,%1,%2,%3},{%4,%5,%6,%7},{%8,%9},{%0,%1,%2,%3};\n"
        : "+f"(c[0]), "+f"(c[1]), "+f"(c[2]), "+f"(c[3])
        : "r"(a[0]), "r"(a[1]), "r"(a[2]), "r"(a[3]), "r"(b[0]), "r"(b[1]));
}

__device__ __forceinline__ void cpa16(uint32_t dst, const void* src) {
    asm volatile("cp.async.cg.shared.global [%0], [%1], 16;" :: "r"(dst), "l"(src));
}
#define CPA_COMMIT() asm volatile("cp.async.commit_group;" ::: "memory")
#define CPA_WAIT(n)  asm volatile("cp.async.wait_group %0;" :: "n"(n) : "memory")

// ---------------------------------------------------------------------------
// tf32 rounding pre-pass
// ---------------------------------------------------------------------------
__global__ void round_tf32_k(const float4* __restrict__ in, float4* __restrict__ out, int n4) {
    int i = blockIdx.x * blockDim.x + threadIdx.x;
    int stride = gridDim.x * blockDim.x;
    for (; i < n4; i += stride) {
        float4 v = in[i];
        v.x = tf32r(v.x); v.y = tf32r(v.y); v.z = tf32r(v.z); v.w = tf32r(v.w);
        out[i] = v;
    }
}

// ---------------------------------------------------------------------------
// GEMM: C[m][n] = sum_k A[m][k] * W[n][k]  (4096^3), pre-rounded tf32 inputs.
// CTA 128x256, BK=32, 8 warps, warp tile 64x64, 3-stage cp.async pipeline.
// doRope: fused RoPE epilogue.
// ---------------------------------------------------------------------------
#define BM 128
#define BN 256
#define BK 32
#define SSTR 36
#define ABUF (BM * SSTR)                  // floats
#define BBUF (BN * SSTR)
#define SPF  (ABUF + BBUF)                // floats per stage = 13824
#define NSTG 3
#define GS   (NSTG * SPF * 4)             // 165888 B
#define NKT  (MAT / BK)                   // 128

__global__ __launch_bounds__(256, 1) void gemm_simt(
    const float* __restrict__ A, const float* __restrict__ W, float* __restrict__ C,
    const float* __restrict__ cosT, const float* __restrict__ sinT, int doRope)
{
    extern __shared__ float sm[];
    const uint32_t smb = smem_u32(sm);

    const int tid = threadIdx.x;
    const int bn = blockIdx.x, bm = blockIdx.y;

    // cp.async issue for K-tile i into stage i % NSTG
    const float* Abase = A + (size_t)(bm * BM) * MAT;
    const float* Wbase = W + (size_t)(bn * BN) * MAT;

    auto issue = [&](int i) {
        const uint32_t as = smb + (uint32_t)((i % NSTG) * SPF) * 4u;
        const uint32_t bs = as + ABUF * 4u;
        const int kb = i * BK;
#pragma unroll
        for (int j = 0; j < 4; j++) {          // A: 128 rows x 2 chunks... 1024 chunks
            const int idx = tid + j * 256;
            const int r = idx >> 3, cc = (idx & 7) << 2;
            cpa16(as + (uint32_t)(r * SSTR + cc) * 4u,
                  Abase + (size_t)r * MAT + kb + cc);
        }
#pragma unroll
        for (int j = 0; j < 8; j++) {          // B: 256 rows -> 2048 chunks
            const int idx = tid + j * 256;
            const int r = idx >> 3, cc = (idx & 7) << 2;
            cpa16(bs + (uint32_t)(r * SSTR + cc) * 4u,
                  Wbase + (size_t)r * MAT + kb + cc);
        }
        CPA_COMMIT();
    };

    issue(0);
    issue(1);

    const int lane = tid & 31, wrp = tid >> 5;
    const int g = lane >> 2, t = lane & 3;
    const int m0 = (wrp & 1) * 64;            // 2 M-slots
    const int n0 = (wrp >> 1) * 64;           // 4 N-slots

    float acc[4][8][4];
#pragma unroll
    for (int a = 0; a < 4; a++)
#pragma unroll
        for (int b = 0; b < 8; b++)
#pragma unroll
            for (int c = 0; c < 4; c++) acc[a][b][c] = 0.f;

    CPA_WAIT(1);
    __syncthreads();

    for (int kt = 0; kt < NKT; kt++) {
        const bool more2 = (kt + 2 < NKT), more1 = (kt + 1 < NKT);
        if (more2) issue(kt + 2);

        const float* stage = sm + (kt % NSTG) * SPF;
        const uint32_t* au = reinterpret_cast<const uint32_t*>(stage);
        const uint32_t* bu = reinterpret_cast<const uint32_t*>(stage + ABUF);

#pragma unroll
        for (int ks = 0; ks < 4; ks++) {
            const int k0 = ks * 8;
            uint32_t af[4][4];
#pragma unroll
            for (int mt = 0; mt < 4; mt++) {
                const int r = m0 + mt * 16 + g;
                af[mt][0] = au[r * SSTR + k0 + t];
                af[mt][1] = au[(r + 8) * SSTR + k0 + t];
                af[mt][2] = au[r * SSTR + k0 + t + 4];
                af[mt][3] = au[(r + 8) * SSTR + k0 + t + 4];
            }
#pragma unroll
            for (int nt = 0; nt < 8; nt++) {
                const int n = n0 + nt * 8 + g;
                uint32_t bf[2] = { bu[n * SSTR + k0 + t], bu[n * SSTR + k0 + t + 4] };
                mma8(acc[0][nt], af[0], bf);
                mma8(acc[1][nt], af[1], bf);
                mma8(acc[2][nt], af[2], bf);
                mma8(acc[3][nt], af[3], bf);
            }
        }

        if (more1) {
            if (more2) { CPA_WAIT(1); } else { CPA_WAIT(0); }
            __syncthreads();
        }
    }

    // epilogue (+ fused RoPE)
#pragma unroll
    for (int mt = 0; mt < 4; mt++) {
        const int gm = bm * BM + m0 + mt * 16 + g;
        const int s0 = gm & (SQ - 1);
#pragma unroll
        for (int nt = 0; nt < 8; nt++) {
            const int cloc = n0 + nt * 8 + 2 * t;
            const int gn = bn * BN + cloc;
            float v0 = acc[mt][nt][0], v1 = acc[mt][nt][1];
            float v2 = acc[mt][nt][2], v3 = acc[mt][nt][3];
            if (doRope) {
                const int p = (cloc & 127) >> 1;
                const float cc0 = cosT[s0 * 64 + p],       ss0 = sinT[s0 * 64 + p];
                const float cc1 = cosT[(s0 + 8) * 64 + p], ss1 = sinT[(s0 + 8) * 64 + p];
                const float w0 = v0 * cc0 - v1 * ss0;
                const float w1 = v0 * ss0 + v1 * cc0;
                const float w2 = v2 * cc1 - v3 * ss1;
                const float w3 = v2 * ss1 + v3 * cc1;
                v0 = w0; v1 = w1; v2 = w2; v3 = w3;
            }
            *reinterpret_cast<float2*>(C + (size_t)gm * MAT + gn)       = make_float2(v0, v1);
            *reinterpret_cast<float2*>(C + (size_t)(gm + 8) * MAT + gn) = make_float2(v2, v3);
        }
    }
}

// ---------------------------------------------------------------------------
// Flash attention (proven R1 kernel; rounds its own inputs, rounds output so
// the Wo GEMM reads exact-tf32 values).
// ---------------------------------------------------------------------------
#define QSTR 132
#define KSTR 132
#define VSTR 136
#define PSTR 68

__global__ __launch_bounds__(256, 1) void attn128(
    const float* __restrict__ Q, const float* __restrict__ K,
    const float* __restrict__ V, float* __restrict__ O)
{
    extern __shared__ float sm[];
    float* Qs = sm;
    float* Ks = Qs + 128 * QSTR;
    float* Vs = Ks + 64 * KSTR;
    float* Ps = Vs + 64 * VSTR;

    const int tid = threadIdx.x;
    const int qt = blockIdx.x, h = blockIdx.y, b = blockIdx.z;
    const int qbase = qt * 128;
    const size_t rowbase = (size_t)b * SQ;
    const float scale = 0.08838834764831845f;

    {
        const float* qp = Q + (rowbase + qbase) * MAT + h * HD;
#pragma unroll
        for (int i = 0; i < 16; i++) {
            int idx = tid + i * 256;
            int row = idx >> 5;
            int c4  = (idx & 31) << 2;
            float4 v = *reinterpret_cast<const float4*>(qp + (size_t)row * MAT + c4);
            v.x = tf32r(v.x * scale); v.y = tf32r(v.y * scale);
            v.z = tf32r(v.z * scale); v.w = tf32r(v.w * scale);
            *reinterpret_cast<float4*>(Qs + row * QSTR + c4) = v;
        }
    }

    const int lane = tid & 31, wrp = tid >> 5;
    const int g = lane >> 2, t = lane & 3;
    const int r0 = wrp * 16;

    float o[16][4];
#pragma unroll
    for (int i = 0; i < 16; i++)
#pragma unroll
        for (int j = 0; j < 4; j++) o[i][j] = 0.f;
    float m0 = NEG_BIG, m1 = NEG_BIG, l0 = 0.f, l1 = 0.f;

    const int nkt = 2 * qt + 2;
    for (int kt = 0; kt < nkt; kt++) {
        __syncthreads();
        {
            const float* kp = K + (rowbase + kt * 64) * MAT + h * HD;
            const float* vp = V + (rowbase + kt * 64) * MAT + h * HD;
#pragma unroll
            for (int i = 0; i < 8; i++) {
                int idx = tid + i * 256;
                int row = idx >> 5;
                int c4  = (idx & 31) << 2;
                float4 kv = *reinterpret_cast<const float4*>(kp + (size_t)row * MAT + c4);
                kv.x = tf32r(kv.x); kv.y = tf32r(kv.y); kv.z = tf32r(kv.z); kv.w = tf32r(kv.w);
                *reinterpret_cast<float4*>(Ks + row * KSTR + c4) = kv;
                float4 vv = *reinterpret_cast<const float4*>(vp + (size_t)row * MAT + c4);
                vv.x = tf32r(vv.x); vv.y = tf32r(vv.y); vv.z = tf32r(vv.z); vv.w = tf32r(vv.w);
                *reinterpret_cast<float4*>(Vs + row * VSTR + c4) = vv;
            }
        }
        __syncthreads();

        float sfr[8][4];
#pragma unroll
        for (int i = 0; i < 8; i++)
#pragma unroll
            for (int j = 0; j < 4; j++) sfr[i][j] = 0.f;

        const uint32_t* qsu = reinterpret_cast<const uint32_t*>(Qs);
        const uint32_t* ksu = reinterpret_cast<const uint32_t*>(Ks);
#pragma unroll
        for (int ks = 0; ks < 16; ks++) {
            const int k0 = ks * 8;
            uint32_t af[4] = {
                qsu[(r0 + g) * QSTR + k0 + t],
                qsu[(r0 + g + 8) * QSTR + k0 + t],
                qsu[(r0 + g) * QSTR + k0 + t + 4],
                qsu[(r0 + g + 8) * QSTR + k0 + t + 4] };
#pragma unroll
            for (int nt = 0; nt < 8; nt++) {
                uint32_t bf[2] = { ksu[(nt * 8 + g) * KSTR + k0 + t],
                                   ksu[(nt * 8 + g) * KSTR + k0 + t + 4] };
                mma8(sfr[nt], af, bf);
            }
        }

        if (kt >= 2 * qt) {
            const int qg0 = qbase + r0 + g;
            const int qg1 = qg0 + 8;
#pragma unroll
            for (int nt = 0; nt < 8; nt++) {
                const int kg = kt * 64 + nt * 8 + 2 * t;
                if (kg     > qg0) sfr[nt][0] = NEG_BIG;
                if (kg + 1 > qg0) sfr[nt][1] = NEG_BIG;
                if (kg     > qg1) sfr[nt][2] = NEG_BIG;
                if (kg + 1 > qg1) sfr[nt][3] = NEG_BIG;
            }
        }

        float tm0 = NEG_BIG, tm1 = NEG_BIG;
#pragma unroll
        for (int nt = 0; nt < 8; nt++) {
            tm0 = fmaxf(tm0, fmaxf(sfr[nt][0], sfr[nt][1]));
            tm1 = fmaxf(tm1, fmaxf(sfr[nt][2], sfr[nt][3]));
        }
        tm0 = fmaxf(tm0, __shfl_xor_sync(0xffffffffu, tm0, 1));
        tm0 = fmaxf(tm0, __shfl_xor_sync(0xffffffffu, tm0, 2));
        tm1 = fmaxf(tm1, __shfl_xor_sync(0xffffffffu, tm1, 1));
        tm1 = fmaxf(tm1, __shfl_xor_sync(0xffffffffu, tm1, 2));

        const float mn0 = fmaxf(m0, tm0), mn1 = fmaxf(m1, tm1);
        const float a0 = __expf(m0 - mn0), a1 = __expf(m1 - mn1);
        float ls0 = 0.f, ls1 = 0.f;
        float* Pw = Ps + wrp * 16 * PSTR;
#pragma unroll
        for (int nt = 0; nt < 8; nt++) {
            const int col = nt * 8 + 2 * t;
            float p0 = __expf(sfr[nt][0] - mn0);
            float p1 = __expf(sfr[nt][1] - mn0);
            float p2 = __expf(sfr[nt][2] - mn1);
            float p3 = __expf(sfr[nt][3] - mn1);
            ls0 += p0 + p1; ls1 += p2 + p3;
            Pw[g * PSTR + col]           = tf32r(p0);
            Pw[g * PSTR + col + 1]       = tf32r(p1);
            Pw[(g + 8) * PSTR + col]     = tf32r(p2);
            Pw[(g + 8) * PSTR + col + 1] = tf32r(p3);
        }
        ls0 += __shfl_xor_sync(0xffffffffu, ls0, 1);
        ls0 += __shfl_xor_sync(0xffffffffu, ls0, 2);
        ls1 += __shfl_xor_sync(0xffffffffu, ls1, 1);
        ls1 += __shfl_xor_sync(0xffffffffu, ls1, 2);
        l0 = l0 * a0 + ls0;
        l1 = l1 * a1 + ls1;
        m0 = mn0; m1 = mn1;
#pragma unroll
        for (int nt = 0; nt < 16; nt++) {
            o[nt][0] *= a0; o[nt][1] *= a0; o[nt][2] *= a1; o[nt][3] *= a1;
        }
        __syncwarp();

        const uint32_t* pu = reinterpret_cast<const uint32_t*>(Pw);
        const uint32_t* vu = reinterpret_cast<const uint32_t*>(Vs);
#pragma unroll
        for (int ks = 0; ks < 8; ks++) {
            const int k0 = ks * 8;
            uint32_t af[4] = {
                pu[g * PSTR + k0 + t],
                pu[(g + 8) * PSTR + k0 + t],
                pu[g * PSTR + k0 + t + 4],
                pu[(g + 8) * PSTR + k0 + t + 4] };
#pragma unroll
            for (int nt = 0; nt < 16; nt++) {
                uint32_t bf[2] = { vu[(k0 + t) * VSTR + nt * 8 + g],
                                   vu[(k0 + t + 4) * VSTR + nt * 8 + g] };
                mma8(o[nt], af, bf);
            }
        }
    }

    const float inv0 = 1.f / l0, inv1 = 1.f / l1;
    float* op  = O + (rowbase + qbase + r0 + g) * MAT + h * HD;
    float* op2 = op + (size_t)8 * MAT;
#pragma unroll
    for (int nt = 0; nt < 16; nt++) {
        const int col = nt * 8 + 2 * t;
        *reinterpret_cast<float2*>(op + col)  =
            make_float2(tf32r(o[nt][0] * inv0), tf32r(o[nt][1] * inv0));
        *reinterpret_cast<float2*>(op2 + col) =
            make_float2(tf32r(o[nt][2] * inv1), tf32r(o[nt][3] * inv1));
    }
}

// ---------------------------------------------------------------------------
#define ATTN_SMEM ((128 * QSTR + 64 * KSTR + 64 * VSTR + 8 * 16 * PSTR) * 4)

extern "C" void kernel_launch(void* const* d_in, const int* in_sizes, int n_in,
                              void* d_out, int out_size)
{
    const float* x    = (const float*)d_in[0];
    const float* wq   = (const float*)d_in[1];
    const float* wk   = (const float*)d_in[2];
    const float* wv   = (const float*)d_in[3];
    const float* wo   = (const float*)d_in[4];
    const float* cosT = (const float*)d_in[5];
    const float* sinT = (const float*)d_in[6];
    float* out = (float*)d_out;

    cudaFuncSetAttribute(gemm_simt, cudaFuncAttributeMaxDynamicSharedMemorySize, GS);
    cudaFuncSetAttribute(attn128,  cudaFuncAttributeMaxDynamicSharedMemorySize, ATTN_SMEM);

    float *pq, *pk, *pv, *pa, *pxr, *pwq, *pwk, *pwv, *pwo;
    cudaGetSymbolAddress((void**)&pq,  g_q);
    cudaGetSymbolAddress((void**)&pk,  g_k);
    cudaGetSymbolAddress((void**)&pv,  g_v);
    cudaGetSymbolAddress((void**)&pa,  g_att);
    cudaGetSymbolAddress((void**)&pxr, g_xr);
    cudaGetSymbolAddress((void**)&pwq, g_wqr);
    cudaGetSymbolAddress((void**)&pwk, g_wkr);
    cudaGetSymbolAddress((void**)&pwv, g_wvr);
    cudaGetSymbolAddress((void**)&pwo, g_wor);

    const int n4 = (MAT * MAT) / 4;
    round_tf32_k<<<2048, 256>>>((const float4*)x,  (float4*)pxr, n4);
    round_tf32_k<<<2048, 256>>>((const float4*)wq, (float4*)pwq, n4);
    round_tf32_k<<<2048, 256>>>((const float4*)wk, (float4*)pwk, n4);
    round_tf32_k<<<2048, 256>>>((const float4*)wv, (float4*)pwv, n4);
    round_tf32_k<<<2048, 256>>>((const float4*)wo, (float4*)pwo, n4);

    dim3 gg(MAT / BN, MAT / BM);   // (16, 32)
    gemm_simt<<<gg, 256, GS>>>(pxr, pwq, pq, cosT, sinT, 1);
    gemm_simt<<<gg, 256, GS>>>(pxr, pwk, pk, cosT, sinT, 1);
    gemm_simt<<<gg, 256, GS>>>(pxr, pwv, pv, cosT, sinT, 0);
    attn128<<<dim3(8, 32, 4), 256, ATTN_SMEM>>>(pq, pk, pv, pa);
    gemm_simt<<<gg, 256, GS>>>(pa, pwo, out, cosT, sinT, 0);
}

// round 5
// speedup vs baseline: 1.1696x; 1.1068x over previous
#include <cuda_runtime.h>
#include <cstdint>

#define MAT 4096
#define SQ  1024
#define HD  128
#define NEG_BIG (-1e30f)

// Scratch (allocation-free rule: device globals)
__device__ float g_q  [(size_t)MAT * MAT];
__device__ float g_k  [(size_t)MAT * MAT];
__device__ float g_v  [(size_t)MAT * MAT];
__device__ float g_att[(size_t)MAT * MAT];
__device__ float g_xr [(size_t)MAT * MAT];
__device__ float g_wqr[(size_t)MAT * MAT];
__device__ float g_wkr[(size_t)MAT * MAT];
__device__ float g_wvr[(size_t)MAT * MAT];
__device__ float g_wor[(size_t)MAT * MAT];

// ---------------------------------------------------------------------------
__device__ __forceinline__ float tf32r(float x) {
    uint32_t u;
    asm("cvt.rna.tf32.f32 %0, %1;" : "=r"(u) : "f"(x));
    return __uint_as_float(u);
}

__device__ __forceinline__ uint32_t smem_u32(const void* p) {
    uint32_t a;
    asm("{ .reg .u64 t; cvta.to.shared.u64 t, %1; cvt.u32.u64 %0, t; }" : "=r"(a) : "l"(p));
    return a;
}

__device__ __forceinline__ void mma8(float c[4], const uint32_t a[4], const uint32_t b[2]) {
    asm volatile(
        "mma.sync.aligned.m16n8k8.row.col.f32.tf32.tf32.f32 "
        "{%0,%1,%2,%3},{%4,%5,%6,%7},{%8,%9},{%0,%1,%2,%3};\n"
        : "+f"(c[0]), "+f"(c[1]), "+f"(c[2]), "+f"(c[3])
        : "r"(a[0]), "r"(a[1]), "r"(a[2]), "r"(a[3]), "r"(b[0]), "r"(b[1]));
}

__device__ __forceinline__ void cpa16(uint32_t dst, const void* src) {
    asm volatile("cp.async.cg.shared.global [%0], [%1], 16;" :: "r"(dst), "l"(src));
}
#define CPA_COMMIT() asm volatile("cp.async.commit_group;" ::: "memory")
#define CPA_WAIT(n)  asm volatile("cp.async.wait_group %0;" :: "n"(n) : "memory")

// ---------------------------------------------------------------------------
// tf32 rounding pre-pass
// ---------------------------------------------------------------------------
__global__ void round_tf32_k(const float4* __restrict__ in, float4* __restrict__ out, int n4) {
    int i = blockIdx.x * blockDim.x + threadIdx.x;
    int stride = gridDim.x * blockDim.x;
    for (; i < n4; i += stride) {
        float4 v = in[i];
        v.x = tf32r(v.x); v.y = tf32r(v.y); v.z = tf32r(v.z); v.w = tf32r(v.w);
        out[i] = v;
    }
}

// ---------------------------------------------------------------------------
// GEMM: C[m][n] = sum_k A[m][k] * W[n][k]  (4096^3), pre-rounded tf32 inputs.
// CTA 128x128, BK=32, 8 warps (warp tile 32x64), 3-stage cp.async pipeline.
// smem 110.6KB -> 2 CTAs/SM (4 warps/SMSP) for latency hiding.
// ---------------------------------------------------------------------------
#define BM 128
#define BN 128
#define BK 32
#define SSTR 36
#define ABUF (BM * SSTR)                  // 4608 floats
#define BBUF (BN * SSTR)
#define SPF  (ABUF + BBUF)                // 9216 floats / stage
#define NSTG 3
#define GS   (NSTG * SPF * 4)             // 110592 B
#define NKT  (MAT / BK)                   // 128

__global__ __launch_bounds__(256, 2) void gemm_simt(
    const float* __restrict__ A, const float* __restrict__ W, float* __restrict__ C,
    const float* __restrict__ cosT, const float* __restrict__ sinT, int doRope)
{
    extern __shared__ float sm[];
    const uint32_t smb = smem_u32(sm);

    const int tid = threadIdx.x;
    const int bn = blockIdx.x, bm = blockIdx.y;

    const float* Abase = A + (size_t)(bm * BM) * MAT;
    const float* Wbase = W + (size_t)(bn * BN) * MAT;

    auto issue = [&](int i) {
        const uint32_t as = smb + (uint32_t)((i % NSTG) * SPF) * 4u;
        const uint32_t bs = as + ABUF * 4u;
        const int kb = i * BK;
#pragma unroll
        for (int j = 0; j < 4; j++) {          // A: 1024 16B-chunks
            const int idx = tid + j * 256;
            const int r = idx >> 3, cc = (idx & 7) << 2;
            cpa16(as + (uint32_t)(r * SSTR + cc) * 4u,
                  Abase + (size_t)r * MAT + kb + cc);
        }
#pragma unroll
        for (int j = 0; j < 4; j++) {          // B: 1024 16B-chunks
            const int idx = tid + j * 256;
            const int r = idx >> 3, cc = (idx & 7) << 2;
            cpa16(bs + (uint32_t)(r * SSTR + cc) * 4u,
                  Wbase + (size_t)r * MAT + kb + cc);
        }
        CPA_COMMIT();
    };

    issue(0);
    issue(1);

    const int lane = tid & 31, wrp = tid >> 5;
    const int g = lane >> 2, t = lane & 3;
    const int m0 = (wrp & 3) * 32;            // 4 M-slots
    const int n0 = (wrp >> 2) * 64;           // 2 N-slots

    float acc[2][8][4];
#pragma unroll
    for (int a = 0; a < 2; a++)
#pragma unroll
        for (int b = 0; b < 8; b++)
#pragma unroll
            for (int c = 0; c < 4; c++) acc[a][b][c] = 0.f;

    CPA_WAIT(1);
    __syncthreads();

    for (int kt = 0; kt < NKT; kt++) {
        const bool more2 = (kt + 2 < NKT), more1 = (kt + 1 < NKT);
        if (more2) issue(kt + 2);

        const float* stage = sm + (kt % NSTG) * SPF;
        const uint32_t* au = reinterpret_cast<const uint32_t*>(stage);
        const uint32_t* bu = reinterpret_cast<const uint32_t*>(stage + ABUF);

#pragma unroll
        for (int ks = 0; ks < 4; ks++) {
            const int k0 = ks * 8;
            uint32_t af[2][4];
#pragma unroll
            for (int mt = 0; mt < 2; mt++) {
                const int r = m0 + mt * 16 + g;
                af[mt][0] = au[r * SSTR + k0 + t];
                af[mt][1] = au[(r + 8) * SSTR + k0 + t];
                af[mt][2] = au[r * SSTR + k0 + t + 4];
                af[mt][3] = au[(r + 8) * SSTR + k0 + t + 4];
            }
#pragma unroll
            for (int nt = 0; nt < 8; nt++) {
                const int n = n0 + nt * 8 + g;
                uint32_t bf[2] = { bu[n * SSTR + k0 + t], bu[n * SSTR + k0 + t + 4] };
                mma8(acc[0][nt], af[0], bf);
                mma8(acc[1][nt], af[1], bf);
            }
        }

        if (more1) {
            if (more2) { CPA_WAIT(1); } else { CPA_WAIT(0); }
            __syncthreads();
        }
    }

    // epilogue (+ fused RoPE)
#pragma unroll
    for (int mt = 0; mt < 2; mt++) {
        const int gm = bm * BM + m0 + mt * 16 + g;
        const int s0 = gm & (SQ - 1);
#pragma unroll
        for (int nt = 0; nt < 8; nt++) {
            const int cloc = n0 + nt * 8 + 2 * t;       // < 128
            const int gn = bn * BN + cloc;
            float v0 = acc[mt][nt][0], v1 = acc[mt][nt][1];
            float v2 = acc[mt][nt][2], v3 = acc[mt][nt][3];
            if (doRope) {
                const int p = cloc >> 1;                // pair index within head
                const float cc0 = cosT[s0 * 64 + p],       ss0 = sinT[s0 * 64 + p];
                const float cc1 = cosT[(s0 + 8) * 64 + p], ss1 = sinT[(s0 + 8) * 64 + p];
                const float w0 = v0 * cc0 - v1 * ss0;
                const float w1 = v0 * ss0 + v1 * cc0;
                const float w2 = v2 * cc1 - v3 * ss1;
                const float w3 = v2 * ss1 + v3 * cc1;
                v0 = w0; v1 = w1; v2 = w2; v3 = w3;
            }
            *reinterpret_cast<float2*>(C + (size_t)gm * MAT + gn)       = make_float2(v0, v1);
            *reinterpret_cast<float2*>(C + (size_t)(gm + 8) * MAT + gn) = make_float2(v2, v3);
        }
    }
}

// ---------------------------------------------------------------------------
// Flash attention (proven kernel, unchanged).
// ---------------------------------------------------------------------------
#define QSTR 132
#define KSTR 132
#define VSTR 136
#define PSTR 68

__global__ __launch_bounds__(256, 1) void attn128(
    const float* __restrict__ Q, const float* __restrict__ K,
    const float* __restrict__ V, float* __restrict__ O)
{
    extern __shared__ float sm[];
    float* Qs = sm;
    float* Ks = Qs + 128 * QSTR;
    float* Vs = Ks + 64 * KSTR;
    float* Ps = Vs + 64 * VSTR;

    const int tid = threadIdx.x;
    const int qt = blockIdx.x, h = blockIdx.y, b = blockIdx.z;
    const int qbase = qt * 128;
    const size_t rowbase = (size_t)b * SQ;
    const float scale = 0.08838834764831845f;

    {
        const float* qp = Q + (rowbase + qbase) * MAT + h * HD;
#pragma unroll
        for (int i = 0; i < 16; i++) {
            int idx = tid + i * 256;
            int row = idx >> 5;
            int c4  = (idx & 31) << 2;
            float4 v = *reinterpret_cast<const float4*>(qp + (size_t)row * MAT + c4);
            v.x = tf32r(v.x * scale); v.y = tf32r(v.y * scale);
            v.z = tf32r(v.z * scale); v.w = tf32r(v.w * scale);
            *reinterpret_cast<float4*>(Qs + row * QSTR + c4) = v;
        }
    }

    const int lane = tid & 31, wrp = tid >> 5;
    const int g = lane >> 2, t = lane & 3;
    const int r0 = wrp * 16;

    float o[16][4];
#pragma unroll
    for (int i = 0; i < 16; i++)
#pragma unroll
        for (int j = 0; j < 4; j++) o[i][j] = 0.f;
    float m0 = NEG_BIG, m1 = NEG_BIG, l0 = 0.f, l1 = 0.f;

    const int nkt = 2 * qt + 2;
    for (int kt = 0; kt < nkt; kt++) {
        __syncthreads();
        {
            const float* kp = K + (rowbase + kt * 64) * MAT + h * HD;
            const float* vp = V + (rowbase + kt * 64) * MAT + h * HD;
#pragma unroll
            for (int i = 0; i < 8; i++) {
                int idx = tid + i * 256;
                int row = idx >> 5;
                int c4  = (idx & 31) << 2;
                float4 kv = *reinterpret_cast<const float4*>(kp + (size_t)row * MAT + c4);
                kv.x = tf32r(kv.x); kv.y = tf32r(kv.y); kv.z = tf32r(kv.z); kv.w = tf32r(kv.w);
                *reinterpret_cast<float4*>(Ks + row * KSTR + c4) = kv;
                float4 vv = *reinterpret_cast<const float4*>(vp + (size_t)row * MAT + c4);
                vv.x = tf32r(vv.x); vv.y = tf32r(vv.y); vv.z = tf32r(vv.z); vv.w = tf32r(vv.w);
                *reinterpret_cast<float4*>(Vs + row * VSTR + c4) = vv;
            }
        }
        __syncthreads();

        float sfr[8][4];
#pragma unroll
        for (int i = 0; i < 8; i++)
#pragma unroll
            for (int j = 0; j < 4; j++) sfr[i][j] = 0.f;

        const uint32_t* qsu = reinterpret_cast<const uint32_t*>(Qs);
        const uint32_t* ksu = reinterpret_cast<const uint32_t*>(Ks);
#pragma unroll
        for (int ks = 0; ks < 16; ks++) {
            const int k0 = ks * 8;
            uint32_t af[4] = {
                qsu[(r0 + g) * QSTR + k0 + t],
                qsu[(r0 + g + 8) * QSTR + k0 + t],
                qsu[(r0 + g) * QSTR + k0 + t + 4],
                qsu[(r0 + g + 8) * QSTR + k0 + t + 4] };
#pragma unroll
            for (int nt = 0; nt < 8; nt++) {
                uint32_t bf[2] = { ksu[(nt * 8 + g) * KSTR + k0 + t],
                                   ksu[(nt * 8 + g) * KSTR + k0 + t + 4] };
                mma8(sfr[nt], af, bf);
            }
        }

        if (kt >= 2 * qt) {
            const int qg0 = qbase + r0 + g;
            const int qg1 = qg0 + 8;
#pragma unroll
            for (int nt = 0; nt < 8; nt++) {
                const int kg = kt * 64 + nt * 8 + 2 * t;
                if (kg     > qg0) sfr[nt][0] = NEG_BIG;
                if (kg + 1 > qg0) sfr[nt][1] = NEG_BIG;
                if (kg     > qg1) sfr[nt][2] = NEG_BIG;
                if (kg + 1 > qg1) sfr[nt][3] = NEG_BIG;
            }
        }

        float tm0 = NEG_BIG, tm1 = NEG_BIG;
#pragma unroll
        for (int nt = 0; nt < 8; nt++) {
            tm0 = fmaxf(tm0, fmaxf(sfr[nt][0], sfr[nt][1]));
            tm1 = fmaxf(tm1, fmaxf(sfr[nt][2], sfr[nt][3]));
        }
        tm0 = fmaxf(tm0, __shfl_xor_sync(0xffffffffu, tm0, 1));
        tm0 = fmaxf(tm0, __shfl_xor_sync(0xffffffffu, tm0, 2));
        tm1 = fmaxf(tm1, __shfl_xor_sync(0xffffffffu, tm1, 1));
        tm1 = fmaxf(tm1, __shfl_xor_sync(0xffffffffu, tm1, 2));

        const float mn0 = fmaxf(m0, tm0), mn1 = fmaxf(m1, tm1);
        const float a0 = __expf(m0 - mn0), a1 = __expf(m1 - mn1);
        float ls0 = 0.f, ls1 = 0.f;
        float* Pw = Ps + wrp * 16 * PSTR;
#pragma unroll
        for (int nt = 0; nt < 8; nt++) {
            const int col = nt * 8 + 2 * t;
            float p0 = __expf(sfr[nt][0] - mn0);
            float p1 = __expf(sfr[nt][1] - mn0);
            float p2 = __expf(sfr[nt][2] - mn1);
            float p3 = __expf(sfr[nt][3] - mn1);
            ls0 += p0 + p1; ls1 += p2 + p3;
            Pw[g * PSTR + col]           = tf32r(p0);
            Pw[g * PSTR + col + 1]       = tf32r(p1);
            Pw[(g + 8) * PSTR + col]     = tf32r(p2);
            Pw[(g + 8) * PSTR + col + 1] = tf32r(p3);
        }
        ls0 += __shfl_xor_sync(0xffffffffu, ls0, 1);
        ls0 += __shfl_xor_sync(0xffffffffu, ls0, 2);
        ls1 += __shfl_xor_sync(0xffffffffu, ls1, 1);
        ls1 += __shfl_xor_sync(0xffffffffu, ls1, 2);
        l0 = l0 * a0 + ls0;
        l1 = l1 * a1 + ls1;
        m0 = mn0; m1 = mn1;
#pragma unroll
        for (int nt = 0; nt < 16; nt++) {
            o[nt][0] *= a0; o[nt][1] *= a0; o[nt][2] *= a1; o[nt][3] *= a1;
        }
        __syncwarp();

        const uint32_t* pu = reinterpret_cast<const uint32_t*>(Pw);
        const uint32_t* vu = reinterpret_cast<const uint32_t*>(Vs);
#pragma unroll
        for (int ks = 0; ks < 8; ks++) {
            const int k0 = ks * 8;
            uint32_t af[4] = {
                pu[g * PSTR + k0 + t],
                pu[(g + 8) * PSTR + k0 + t],
                pu[g * PSTR + k0 + t + 4],
                pu[(g + 8) * PSTR + k0 + t + 4] };
#pragma unroll
            for (int nt = 0; nt < 16; nt++) {
                uint32_t bf[2] = { vu[(k0 + t) * VSTR + nt * 8 + g],
                                   vu[(k0 + t + 4) * VSTR + nt * 8 + g] };
                mma8(o[nt], af, bf);
            }
        }
    }

    const float inv0 = 1.f / l0, inv1 = 1.f / l1;
    float* op  = O + (rowbase + qbase + r0 + g) * MAT + h * HD;
    float* op2 = op + (size_t)8 * MAT;
#pragma unroll
    for (int nt = 0; nt < 16; nt++) {
        const int col = nt * 8 + 2 * t;
        *reinterpret_cast<float2*>(op + col)  =
            make_float2(tf32r(o[nt][0] * inv0), tf32r(o[nt][1] * inv0));
        *reinterpret_cast<float2*>(op2 + col) =
            make_float2(tf32r(o[nt][2] * inv1), tf32r(o[nt][3] * inv1));
    }
}

// ---------------------------------------------------------------------------
#define ATTN_SMEM ((128 * QSTR + 64 * KSTR + 64 * VSTR + 8 * 16 * PSTR) * 4)

extern "C" void kernel_launch(void* const* d_in, const int* in_sizes, int n_in,
                              void* d_out, int out_size)
{
    const float* x    = (const float*)d_in[0];
    const float* wq   = (const float*)d_in[1];
    const float* wk   = (const float*)d_in[2];
    const float* wv   = (const float*)d_in[3];
    const float* wo   = (const float*)d_in[4];
    const float* cosT = (const float*)d_in[5];
    const float* sinT = (const float*)d_in[6];
    float* out = (float*)d_out;

    cudaFuncSetAttribute(gemm_simt, cudaFuncAttributeMaxDynamicSharedMemorySize, GS);
    cudaFuncSetAttribute(attn128,  cudaFuncAttributeMaxDynamicSharedMemorySize, ATTN_SMEM);

    float *pq, *pk, *pv, *pa, *pxr, *pwq, *pwk, *pwv, *pwo;
    cudaGetSymbolAddress((void**)&pq,  g_q);
    cudaGetSymbolAddress((void**)&pk,  g_k);
    cudaGetSymbolAddress((void**)&pv,  g_v);
    cudaGetSymbolAddress((void**)&pa,  g_att);
    cudaGetSymbolAddress((void**)&pxr, g_xr);
    cudaGetSymbolAddress((void**)&pwq, g_wqr);
    cudaGetSymbolAddress((void**)&pwk, g_wkr);
    cudaGetSymbolAddress((void**)&pwv, g_wvr);
    cudaGetSymbolAddress((void**)&pwo, g_wor);

    const int n4 = (MAT * MAT) / 4;
    round_tf32_k<<<2048, 256>>>((const float4*)x,  (float4*)pxr, n4);
    round_tf32_k<<<2048, 256>>>((const float4*)wq, (float4*)pwq, n4);
    round_tf32_k<<<2048, 256>>>((const float4*)wk, (float4*)pwk, n4);
    round_tf32_k<<<2048, 256>>>((const float4*)wv, (float4*)pwv, n4);
    round_tf32_k<<<2048, 256>>>((const float4*)wo, (float4*)pwo, n4);

    dim3 gg(MAT / BN, MAT / BM);   // (32, 32)
    gemm_simt<<<gg, 256, GS>>>(pxr, pwq, pq, cosT, sinT, 1);
    gemm_simt<<<gg, 256, GS>>>(pxr, pwk, pk, cosT, sinT, 1);
    gemm_simt<<<gg, 256, GS>>>(pxr, pwv, pv, cosT, sinT, 0);
    attn128<<<dim3(8, 32, 4), 256, ATTN_SMEM>>>(pq, pk, pv, pa);
    gemm_simt<<<gg, 256, GS>>>(pa, pwo, out, cosT, sinT, 0);
}